// round 1
// baseline (speedup 1.0000x reference)
#include <cuda_runtime.h>
#include <cstdint>

#define BATCH 8192
#define FEAT  1024
#define NLEAF 64
#define NINT  63
#define LDIM  128
#define OUTD  8192

// Scratch (device globals: allocation-free)
__device__ float g_xa[BATCH * FEAT];          // tf32-rounded x          (32 MB)
__device__ float g_wb[NLEAF * FEAT * LDIM];   // tf32-rounded leaf W     (32 MB)
__device__ float g_dw[FEAT * 64];             // routing diff weights [f][64], col63=0
__device__ float g_part[4][BATCH * 64];       // split-K routing partials (8 MB)
__device__ float g_lp[BATCH * 64];            // leaf probs (2 MB)

__device__ __forceinline__ void cp16(void* s, const void* g) {
    uint32_t sa = (uint32_t)__cvta_generic_to_shared(s);
    asm volatile("cp.async.cg.shared.global [%0], [%1], 16;" ::"r"(sa), "l"(g));
}
__device__ __forceinline__ void cp_commit() { asm volatile("cp.async.commit_group;"); }
template <int N>
__device__ __forceinline__ void cp_wait() { asm volatile("cp.async.wait_group %0;" ::"n"(N)); }

__device__ __forceinline__ float to_tf32(float x) {
    uint32_t r;
    asm("cvt.rna.tf32.f32 %0, %1;" : "=r"(r) : "f"(x));
    return __uint_as_float(r);
}

__device__ __forceinline__ void mma_tf32(float* c, const uint32_t* a, uint32_t b0, uint32_t b1) {
    asm volatile(
        "mma.sync.aligned.m16n8k8.row.col.f32.tf32.tf32.f32 "
        "{%0,%1,%2,%3}, {%4,%5,%6,%7}, {%8,%9}, {%0,%1,%2,%3};\n"
        : "+f"(c[0]), "+f"(c[1]), "+f"(c[2]), "+f"(c[3])
        : "r"(a[0]), "r"(a[1]), "r"(a[2]), "r"(a[3]), "r"(b0), "r"(b1));
}

// ---------------- prep: round fp32 -> tf32 (rna, unbiased) ----------------
__global__ void k_cvt(const float4* __restrict__ src, int which) {
    int i = blockIdx.x * blockDim.x + threadIdx.x;  // exactly 2097152 threads
    float4 v = src[i];
    float4 o;
    o.x = to_tf32(v.x); o.y = to_tf32(v.y); o.z = to_tf32(v.z); o.w = to_tf32(v.w);
    float4* dst = which ? (float4*)g_wb : (float4*)g_xa;
    dst[i] = o;
}

// ---------------- prep: routing diff weights D[f][n] = rw[n,f,0]-rw[n,f,1] ----------------
__global__ void k_dw(const float* __restrict__ rw) {
    int i = blockIdx.x * blockDim.x + threadIdx.x;  // 65536
    int f = i >> 6, n = i & 63;
    float v = 0.f;
    if (n < NINT) v = rw[(n * FEAT + f) * 2] - rw[(n * FEAT + f) * 2 + 1];
    g_dw[f * 64 + n] = v;
}

// ---------------- routing GEMM (fp32 FFMA, deterministic split-K x4) ----------------
// grid (128 row-blocks of 64, 4 k-chunks of 256), 256 threads
__global__ __launch_bounds__(256) void k_rout(const float* __restrict__ x) {
    __shared__ float Xs[2][64][20];
    __shared__ float Ds[2][16][68];
    int tid = threadIdx.x;
    int r0 = blockIdx.x * 64;
    int kc = blockIdx.y * 256;
    int rg = tid >> 4, cg = tid & 15;
    float acc[4][4];
#pragma unroll
    for (int i = 0; i < 4; i++)
#pragma unroll
        for (int j = 0; j < 4; j++) acc[i][j] = 0.f;

    auto load = [&](int s, int k0) {
        {
            int row = tid >> 2, ko = (tid & 3) << 2;
            cp16(&Xs[s][row][ko], x + (size_t)(r0 + row) * FEAT + kc + k0 + ko);
        }
        {
            int row = tid >> 4, no = (tid & 15) << 2;
            cp16(&Ds[s][row][no], g_dw + (kc + k0 + row) * 64 + no);
        }
    };
    load(0, 0); cp_commit();
    load(1, 16); cp_commit();
    cp_wait<1>();
    __syncthreads();

    for (int kt = 0; kt < 16; kt++) {
        int s = kt & 1;
#pragma unroll
        for (int k = 0; k < 16; k++) {
            float4 b = *(const float4*)&Ds[s][k][cg << 2];
#pragma unroll
            for (int i = 0; i < 4; i++) {
                float a = Xs[s][(rg << 2) + i][k];
                acc[i][0] += a * b.x; acc[i][1] += a * b.y;
                acc[i][2] += a * b.z; acc[i][3] += a * b.w;
            }
        }
        __syncthreads();
        if (kt + 2 < 16) load(s, (kt + 2) * 16);
        cp_commit();
        cp_wait<1>();
        __syncthreads();
    }
#pragma unroll
    for (int i = 0; i < 4; i++) {
        float4 v = make_float4(acc[i][0], acc[i][1], acc[i][2], acc[i][3]);
        *(float4*)&g_part[blockIdx.y][(size_t)(r0 + (rg << 2) + i) * 64 + (cg << 2)] = v;
    }
}

// ---------------- leaf probs: sigmoid + 6-level path product ----------------
// complete binary tree, 64 leaves: node(d,l) = (1<<d)-1 + (l >> (6-d)), dir = (l >> (5-d)) & 1
__global__ void k_leaf() {
    __shared__ float ps[8][64];
    int tid = threadIdx.x;  // 512
    int rb = blockIdx.x * 8;
    int r = tid >> 6, n = tid & 63;
    if (n < NINT) {
        size_t idx = (size_t)(rb + r) * 64 + n;
        float s = g_part[0][idx] + g_part[1][idx] + g_part[2][idx] + g_part[3][idx];
        ps[r][n] = 1.f / (1.f + __expf(-s));  // P(dir=0) = softmax[...,0]
    }
    __syncthreads();
    int l = n;
    float prob = 1.f;
#pragma unroll
    for (int d = 0; d < 6; d++) {
        int node = (1 << d) - 1 + (l >> (6 - d));
        int dir = (l >> (5 - d)) & 1;
        float p = ps[r][node];
        prob *= dir ? (1.f - p) : p;
    }
    g_lp[(size_t)(rb + r) * 64 + l] = prob;
}

// ---------------- main GEMM: per (leaf, 128-row block): 128x128x1024 tf32 mma.sync ----------------
// epilogue: out = leaf_prob[row,leaf] * (acc + bias[leaf,col])
__global__ __launch_bounds__(256) void k_main(const float* __restrict__ bias, float* __restrict__ out) {
    __shared__ float As[2][128][20];   // [M][BK] pad-20: conflict-free frag loads
    __shared__ float Bs[2][16][136];   // [BK][N] pad-136: conflict-free frag loads
    const int tid = threadIdx.x, lane = tid & 31, wid = tid >> 5;
    const int leaf = blockIdx.x;
    const int bm0 = blockIdx.y * 128;
    const float* Ag = g_xa + (size_t)bm0 * FEAT;
    const float* Bg = g_wb + (size_t)leaf * (FEAT * LDIM);
    const int mw = (wid & 3) * 32, nw = (wid >> 2) * 64;
    const int g = lane >> 2, cc = lane & 3;

    float acc[2][8][4];
#pragma unroll
    for (int a = 0; a < 2; a++)
#pragma unroll
        for (int b = 0; b < 8; b++)
#pragma unroll
            for (int c = 0; c < 4; c++) acc[a][b][c] = 0.f;

    auto load_stage = [&](int s, int k0) {
#pragma unroll
        for (int u = 0; u < 2; u++) {
            int c = tid + u * 256;
            int row = c >> 2, ko = (c & 3) << 2;
            cp16(&As[s][row][ko], Ag + (size_t)row * FEAT + k0 + ko);
        }
#pragma unroll
        for (int u = 0; u < 2; u++) {
            int c = tid + u * 256;
            int row = c >> 5, no = (c & 31) << 2;
            cp16(&Bs[s][row][no], Bg + (size_t)(k0 + row) * LDIM + no);
        }
    };
    load_stage(0, 0); cp_commit();
    load_stage(1, 16); cp_commit();
    cp_wait<1>();
    __syncthreads();

    for (int kt = 0; kt < 64; kt++) {
        int s = kt & 1;
#pragma unroll
        for (int ks = 0; ks < 2; ks++) {
            int kb = ks * 8;
            uint32_t af[2][4];
#pragma unroll
            for (int mt = 0; mt < 2; mt++) {
                int r = mw + mt * 16 + g;
                af[mt][0] = __float_as_uint(As[s][r][kb + cc]);
                af[mt][1] = __float_as_uint(As[s][r + 8][kb + cc]);
                af[mt][2] = __float_as_uint(As[s][r][kb + cc + 4]);
                af[mt][3] = __float_as_uint(As[s][r + 8][kb + cc + 4]);
            }
#pragma unroll
            for (int nt = 0; nt < 8; nt++) {
                int n = nw + nt * 8 + g;
                uint32_t b0 = __float_as_uint(Bs[s][kb + cc][n]);
                uint32_t b1 = __float_as_uint(Bs[s][kb + cc + 4][n]);
                mma_tf32(acc[0][nt], af[0], b0, b1);
                mma_tf32(acc[1][nt], af[1], b0, b1);
            }
        }
        __syncthreads();
        if (kt + 2 < 64) load_stage(s, (kt + 2) * 16);
        cp_commit();
        cp_wait<1>();
        __syncthreads();
    }

#pragma unroll
    for (int mt = 0; mt < 2; mt++) {
        int r0 = bm0 + mw + mt * 16 + g;
        float p0 = g_lp[(size_t)r0 * 64 + leaf];
        float p1 = g_lp[(size_t)(r0 + 8) * 64 + leaf];
#pragma unroll
        for (int nt = 0; nt < 8; nt++) {
            int col = nw + nt * 8 + 2 * cc;
            float b0 = bias[leaf * LDIM + col];
            float b1 = bias[leaf * LDIM + col + 1];
            int gc = leaf * LDIM + col;
            float2 v0 = make_float2(p0 * (acc[mt][nt][0] + b0), p0 * (acc[mt][nt][1] + b1));
            float2 v1 = make_float2(p1 * (acc[mt][nt][2] + b0), p1 * (acc[mt][nt][3] + b1));
            *(float2*)(out + (size_t)r0 * OUTD + gc) = v0;
            *(float2*)(out + (size_t)(r0 + 8) * OUTD + gc) = v1;
        }
    }
}

extern "C" void kernel_launch(void* const* d_in, const int* in_sizes, int n_in,
                              void* d_out, int out_size) {
    const float* x  = (const float*)d_in[0];
    const float* rw = (const float*)d_in[1];
    const float* lw = (const float*)d_in[2];
    const float* lb = (const float*)d_in[3];
    float* out = (float*)d_out;
    (void)in_sizes; (void)n_in; (void)out_size;

    k_cvt<<<8192, 256>>>((const float4*)x, 0);
    k_cvt<<<8192, 256>>>((const float4*)lw, 1);
    k_dw<<<256, 256>>>(rw);
    k_rout<<<dim3(128, 4), 256>>>(x);
    k_leaf<<<1024, 512>>>();
    k_main<<<dim3(64, 64), 256>>>(lb, out);
}

// round 4
// speedup vs baseline: 1.8592x; 1.8592x over previous
#include <cuda_runtime.h>
#include <cuda_fp16.h>
#include <cstdint>

#define BATCH 8192
#define FEAT  1024
#define NLEAF 64
#define LDIM  128
#define OUTD  8192
#define NINT  63

// ---------------- device scratch (no allocations) ----------------
__device__ __half g_xh[BATCH * FEAT];          // fp16 x, row-major [8192][1024]   (16 MB)
__device__ __half g_wh[NLEAF * LDIM * FEAT];   // fp16 W^T, [leaf][o][f]           (16 MB)
__device__ float g_dw[FEAT * 64];              // routing diff weights
__device__ float g_part[4][BATCH * 64];        // routing split-K partials
__device__ float g_lp[BATCH * 64];             // leaf probs

// ---------------- PTX helpers ----------------
__device__ __forceinline__ uint32_t smem_u32(const void* p) {
    uint32_t a;
    asm("{ .reg .u64 t; cvta.to.shared.u64 t, %1; cvt.u32.u64 %0, t; }" : "=r"(a) : "l"(p));
    return a;
}
__device__ __forceinline__ void cp16(void* s, const void* g) {
    uint32_t sa = smem_u32(s);
    asm volatile("cp.async.cg.shared.global [%0], [%1], 16;" ::"r"(sa), "l"(g));
}
__device__ __forceinline__ void cp_commit() { asm volatile("cp.async.commit_group;"); }
template <int N> __device__ __forceinline__ void cp_wait() { asm volatile("cp.async.wait_group %0;" ::"n"(N)); }

__device__ __forceinline__ void ldm4(uint32_t* r, uint32_t addr) {
    asm volatile("ldmatrix.sync.aligned.m8n8.x4.shared.b16 {%0,%1,%2,%3}, [%4];"
        : "=r"(r[0]), "=r"(r[1]), "=r"(r[2]), "=r"(r[3]) : "r"(addr));
}
__device__ __forceinline__ void mma_f16(float* c, const uint32_t* a, uint32_t b0, uint32_t b1) {
    asm volatile(
        "mma.sync.aligned.m16n8k16.row.col.f32.f16.f16.f32 "
        "{%0,%1,%2,%3}, {%4,%5,%6,%7}, {%8,%9}, {%0,%1,%2,%3};\n"
        : "+f"(c[0]), "+f"(c[1]), "+f"(c[2]), "+f"(c[3])
        : "r"(a[0]), "r"(a[1]), "r"(a[2]), "r"(a[3]), "r"(b0), "r"(b1));
}

// ---------------- prep: fp32 -> fp16 (rn) ----------------
__global__ void k_cvt_h(const float4* __restrict__ src) {
    int i = blockIdx.x * blockDim.x + threadIdx.x;  // 2097152 threads = 8M floats
    float4 v = src[i];
    __half2 h0 = __floats2half2_rn(v.x, v.y);
    __half2 h1 = __floats2half2_rn(v.z, v.w);
    uint2 o;
    o.x = *(uint32_t*)&h0;
    o.y = *(uint32_t*)&h1;
    ((uint2*)g_xh)[i] = o;
}

// W transpose + fp16 round: lw[leaf][f][o] -> g_wh[leaf][o][f]
__global__ void k_wt_h(const float* __restrict__ lw) {
    __shared__ float t[32][33];
    int f0 = blockIdx.x * 32, o0 = blockIdx.y * 32, leaf = blockIdx.z;
    int j = threadIdx.x & 31, i0 = threadIdx.x >> 5;
    const float* src = lw + (size_t)leaf * FEAT * LDIM;
#pragma unroll
    for (int p = 0; p < 4; p++) {
        int i = i0 + p * 8;
        t[i][j] = src[(size_t)(f0 + i) * LDIM + o0 + j];
    }
    __syncthreads();
    __half* dst = g_wh + (size_t)leaf * LDIM * FEAT;
#pragma unroll
    for (int p = 0; p < 4; p++) {
        int i = i0 + p * 8;
        dst[(size_t)(o0 + i) * FEAT + f0 + j] = __float2half_rn(t[j][i]);
    }
}

__global__ void k_dw(const float* __restrict__ rw) {
    int i = blockIdx.x * blockDim.x + threadIdx.x;  // 65536
    int f = i >> 6, n = i & 63;
    float v = 0.f;
    if (n < NINT) v = rw[(n * FEAT + f) * 2] - rw[(n * FEAT + f) * 2 + 1];
    g_dw[f * 64 + n] = v;
}

// ---------------- routing GEMM (fp32 FFMA, deterministic split-K x4) ----------------
__global__ __launch_bounds__(256) void k_rout(const float* __restrict__ x) {
    __shared__ float Xs[2][64][20];
    __shared__ float Ds[2][16][68];
    int tid = threadIdx.x;
    int r0 = blockIdx.x * 64;
    int kc = blockIdx.y * 256;
    int rg = tid >> 4, cg = tid & 15;
    float acc[4][4];
#pragma unroll
    for (int i = 0; i < 4; i++)
#pragma unroll
        for (int j = 0; j < 4; j++) acc[i][j] = 0.f;

    auto load = [&](int s, int k0) {
        {
            int row = tid >> 2, ko = (tid & 3) << 2;
            cp16(&Xs[s][row][ko], x + (size_t)(r0 + row) * FEAT + kc + k0 + ko);
        }
        {
            int row = tid >> 4, no = (tid & 15) << 2;
            cp16(&Ds[s][row][no], g_dw + (kc + k0 + row) * 64 + no);
        }
    };
    load(0, 0); cp_commit();
    load(1, 16); cp_commit();
    cp_wait<1>();
    __syncthreads();

    for (int kt = 0; kt < 16; kt++) {
        int s = kt & 1;
#pragma unroll
        for (int k = 0; k < 16; k++) {
            float4 b = *(const float4*)&Ds[s][k][cg << 2];
#pragma unroll
            for (int i = 0; i < 4; i++) {
                float a = Xs[s][(rg << 2) + i][k];
                acc[i][0] += a * b.x; acc[i][1] += a * b.y;
                acc[i][2] += a * b.z; acc[i][3] += a * b.w;
            }
        }
        __syncthreads();
        if (kt + 2 < 16) load(s, (kt + 2) * 16);
        cp_commit();
        cp_wait<1>();
        __syncthreads();
    }
#pragma unroll
    for (int i = 0; i < 4; i++) {
        float4 v = make_float4(acc[i][0], acc[i][1], acc[i][2], acc[i][3]);
        *(float4*)&g_part[blockIdx.y][(size_t)(r0 + (rg << 2) + i) * 64 + (cg << 2)] = v;
    }
}

// ---------------- leaf probs ----------------
__global__ void k_leaf() {
    __shared__ float ps[8][64];
    int tid = threadIdx.x;  // 512
    int rb = blockIdx.x * 8;
    int r = tid >> 6, n = tid & 63;
    if (n < NINT) {
        size_t idx = (size_t)(rb + r) * 64 + n;
        float s = g_part[0][idx] + g_part[1][idx] + g_part[2][idx] + g_part[3][idx];
        ps[r][n] = 1.f / (1.f + __expf(-s));
    }
    __syncthreads();
    int l = n;
    float prob = 1.f;
#pragma unroll
    for (int d = 0; d < 6; d++) {
        int node = (1 << d) - 1 + (l >> (6 - d));
        int dir = (l >> (5 - d)) & 1;
        float p = ps[r][node];
        prob *= dir ? (1.f - p) : p;
    }
    g_lp[(size_t)(rb + r) * 64 + l] = prob;
}

// ---------------- main GEMM: fp16 mma.sync m16n8k16, 128x128x32 staging, ldmatrix ----------------
// smem rows padded to 40 halves (80 B): conflict-free for cp.async fill AND ldmatrix reads.
#define BK 32
#define PAD_K 40

__global__ __launch_bounds__(256, 2) void k_main(const float* __restrict__ bias,
                                                 float* __restrict__ out) {
    __shared__ __half As[2][128][PAD_K];
    __shared__ __half Bs[2][128][PAD_K];
    const int tid = threadIdx.x, lane = tid & 31, wid = tid >> 5;
    const int leaf = blockIdx.x;
    const int bm0 = blockIdx.y * 128;
    const __half* Ag = g_xh + (size_t)bm0 * FEAT;
    const __half* Bg = g_wh + (size_t)leaf * (LDIM * FEAT);
    const int mw = (wid & 3) * 32, nw = (wid >> 2) * 64;
    const int g = lane >> 2, cc = lane & 3;
    const int lr = lane & 7, grp = lane >> 3;

    // per-lane ldmatrix byte offsets (within a stage, before kb-offset)
    // A, mtile mt: row = mw + mt*16 + (grp&1)*8 + lr, col = (grp>>1)*8
    const uint32_t a_off0 = ((mw + (grp & 1) * 8 + lr) * PAD_K + (grp >> 1) * 8) * 2;
    // B, pair pn: row = nw + pn*16 + (grp>>1)*8 + lr, col = (grp&1)*8
    const uint32_t b_off0 = ((nw + (grp >> 1) * 8 + lr) * PAD_K + (grp & 1) * 8) * 2;
    const uint32_t As_base = smem_u32(&As[0][0][0]);
    const uint32_t Bs_base = smem_u32(&Bs[0][0][0]);
    const uint32_t stage_sz = 128 * PAD_K * 2;

    float acc[2][8][4];
#pragma unroll
    for (int a = 0; a < 2; a++)
#pragma unroll
        for (int b = 0; b < 8; b++)
#pragma unroll
            for (int c = 0; c < 4; c++) acc[a][b][c] = 0.f;

    // stage fill: 128 rows x 4 chunks of 16B per matrix; 512 chunks / 256 threads = 2 each
    auto load_stage = [&](int s, int k0) {
#pragma unroll
        for (int u = 0; u < 2; u++) {
            int c = tid + u * 256;
            int row = c >> 2, kc = (c & 3) << 3;
            cp16(&As[s][row][kc], Ag + (size_t)row * FEAT + k0 + kc);
            cp16(&Bs[s][row][kc], Bg + (size_t)row * FEAT + k0 + kc);
        }
    };
    load_stage(0, 0); cp_commit();
    load_stage(1, BK); cp_commit();
    cp_wait<1>();
    __syncthreads();

    for (int kt = 0; kt < FEAT / BK; kt++) {
        int s = kt & 1;
        uint32_t abase = As_base + s * stage_sz + a_off0;
        uint32_t bbase = Bs_base + s * stage_sz + b_off0;
#pragma unroll
        for (int ks = 0; ks < 2; ks++) {
            uint32_t koff = (ks * 16) * 2;
            uint32_t a[2][4], b[4][4];
            ldm4(a[0], abase + koff);
            ldm4(a[1], abase + koff + 16 * PAD_K * 2);
#pragma unroll
            for (int pn = 0; pn < 4; pn++)
                ldm4(b[pn], bbase + koff + pn * 16 * PAD_K * 2);
#pragma unroll
            for (int nt = 0; nt < 8; nt++) {
                int pn = nt >> 1, hi = (nt & 1) << 1;
                mma_f16(acc[0][nt], a[0], b[pn][hi], b[pn][hi + 1]);
                mma_f16(acc[1][nt], a[1], b[pn][hi], b[pn][hi + 1]);
            }
        }
        __syncthreads();
        if (kt + 2 < FEAT / BK) {
            load_stage(s, (kt + 2) * BK);
        }
        cp_commit();
        cp_wait<1>();
        __syncthreads();
    }

    // epilogue: out = p[row,leaf] * (acc + bias[leaf,col])
#pragma unroll
    for (int mt = 0; mt < 2; mt++) {
        int r0 = bm0 + mw + mt * 16 + g;
        float p0 = g_lp[(size_t)r0 * 64 + leaf];
        float p1 = g_lp[(size_t)(r0 + 8) * 64 + leaf];
#pragma unroll
        for (int nt = 0; nt < 8; nt++) {
            int col = nw + nt * 8 + 2 * cc;
            float b0 = bias[leaf * LDIM + col];
            float b1 = bias[leaf * LDIM + col + 1];
            int gc = leaf * LDIM + col;
            float2 v0 = make_float2(p0 * (acc[mt][nt][0] + b0), p0 * (acc[mt][nt][1] + b1));
            float2 v1 = make_float2(p1 * (acc[mt][nt][2] + b0), p1 * (acc[mt][nt][3] + b1));
            *(float2*)(out + (size_t)r0 * OUTD + gc) = v0;
            *(float2*)(out + (size_t)(r0 + 8) * OUTD + gc) = v1;
        }
    }
}

extern "C" void kernel_launch(void* const* d_in, const int* in_sizes, int n_in,
                              void* d_out, int out_size) {
    const float* x  = (const float*)d_in[0];
    const float* rw = (const float*)d_in[1];
    const float* lw = (const float*)d_in[2];
    const float* lb = (const float*)d_in[3];
    float* out = (float*)d_out;
    (void)in_sizes; (void)n_in; (void)out_size;

    k_cvt_h<<<8192, 256>>>((const float4*)x);
    k_wt_h<<<dim3(32, 4, 64), 256>>>(lw);
    k_dw<<<256, 256>>>(rw);
    k_rout<<<dim3(128, 4), 256>>>(x);
    k_leaf<<<1024, 512>>>();
    k_main<<<dim3(64, 64), 256>>>(lb, out);
}

// round 5
// speedup vs baseline: 2.5102x; 1.3502x over previous
#include <cuda_runtime.h>
#include <cuda.h>
#include <cuda_fp16.h>
#include <cstdint>

#define BATCH 8192
#define FEAT  1024
#define NLEAF 64
#define LDIM  128
#define OUTD  8192
#define NINT  63

// ---------------- device scratch (no allocations) ----------------
__device__ __half g_xh[BATCH * FEAT];          // fp16 x, row-major [8192][1024]   (16 MB)
__device__ __half g_wh[NLEAF * LDIM * FEAT];   // fp16 W^T, [leaf][o][f]           (16 MB)
__device__ float g_dw[FEAT * 64];              // routing diff weights
__device__ float g_part[4][BATCH * 64];        // routing split-K partials
__device__ float g_lp[BATCH * 64];             // leaf probs

// ---------------- PTX helpers ----------------
__device__ __forceinline__ uint32_t smem_u32(const void* p) {
    uint32_t a;
    asm("{ .reg .u64 t; cvta.to.shared.u64 t, %1; cvt.u32.u64 %0, t; }" : "=r"(a) : "l"(p));
    return a;
}
__device__ __forceinline__ uint32_t elect_one() {
    uint32_t p;
    asm volatile("{\n\t.reg .pred p;\n\telect.sync _|p, 0xFFFFFFFF;\n\tselp.b32 %0, 1, 0, p;\n\t}" : "=r"(p));
    return p;
}
__device__ __forceinline__ void cp16(void* s, const void* g) {
    uint32_t sa = smem_u32(s);
    asm volatile("cp.async.cg.shared.global [%0], [%1], 16;" ::"r"(sa), "l"(g));
}
__device__ __forceinline__ void cp_commit() { asm volatile("cp.async.commit_group;"); }
template <int N> __device__ __forceinline__ void cp_wait() { asm volatile("cp.async.wait_group %0;" ::"n"(N)); }

#define MBAR_INIT(a, c) asm volatile("mbarrier.init.shared.b64 [%0], %1;" ::"r"(a), "r"(c) : "memory")
#define MBAR_EXPECT_TX(a, n) asm volatile("mbarrier.arrive.expect_tx.shared.b64 _, [%0], %1;" ::"r"(a), "r"(n) : "memory")
#define MBAR_ARRIVE(a) asm volatile("mbarrier.arrive.shared.b64 _, [%0];" ::"r"(a) : "memory")

__device__ __forceinline__ void mbar_wait(uint32_t mbar, uint32_t parity) {
    uint32_t done;
    asm volatile(
        "{\n\t.reg .pred p;\n\t"
        "mbarrier.try_wait.parity.acquire.cta.shared::cta.b64 p, [%1], %2;\n\t"
        "selp.b32 %0, 1, 0, p;\n\t}"
        : "=r"(done) : "r"(mbar), "r"(parity) : "memory");
    if (!done) {
        asm volatile(
            "{\n\t.reg .pred P1;\n\t"
            "WL_%=:\n\t"
            "mbarrier.try_wait.parity.acquire.cta.shared::cta.b64 P1, [%0], %1, 0x989680;\n\t"
            "@P1 bra.uni WD_%=;\n\t"
            "bra.uni WL_%=;\n\t"
            "WD_%=:\n\t}"
            :: "r"(mbar), "r"(parity) : "memory");
    }
}

__device__ __forceinline__ void tma2d(uint32_t sa, const void* map, int cx, int cy, uint32_t mb) {
    asm volatile(
        "cp.async.bulk.tensor.2d.shared::cta.global.tile.mbarrier::complete_tx::bytes "
        "[%0], [%1, {%2, %3}], [%4];"
        :: "r"(sa), "l"(map), "r"(cx), "r"(cy), "r"(mb) : "memory");
}

__device__ __forceinline__ void ldm4(uint32_t* r, uint32_t addr) {
    asm volatile("ldmatrix.sync.aligned.m8n8.x4.shared.b16 {%0,%1,%2,%3}, [%4];"
        : "=r"(r[0]), "=r"(r[1]), "=r"(r[2]), "=r"(r[3]) : "r"(addr));
}
__device__ __forceinline__ void mma_f16(float* c, const uint32_t* a, uint32_t b0, uint32_t b1) {
    asm volatile(
        "mma.sync.aligned.m16n8k16.row.col.f32.f16.f16.f32 "
        "{%0,%1,%2,%3}, {%4,%5,%6,%7}, {%8,%9}, {%0,%1,%2,%3};\n"
        : "+f"(c[0]), "+f"(c[1]), "+f"(c[2]), "+f"(c[3])
        : "r"(a[0]), "r"(a[1]), "r"(a[2]), "r"(a[3]), "r"(b0), "r"(b1));
}

// ---------------- prep: fp32 -> fp16 (rn) ----------------
__global__ void k_cvt_h(const float4* __restrict__ src) {
    int i = blockIdx.x * blockDim.x + threadIdx.x;  // 2097152 threads = 8M floats
    float4 v = src[i];
    __half2 h0 = __floats2half2_rn(v.x, v.y);
    __half2 h1 = __floats2half2_rn(v.z, v.w);
    uint2 o;
    o.x = *(uint32_t*)&h0;
    o.y = *(uint32_t*)&h1;
    ((uint2*)g_xh)[i] = o;
}

// W transpose + fp16 round: lw[leaf][f][o] -> g_wh[leaf][o][f]
__global__ void k_wt_h(const float* __restrict__ lw) {
    __shared__ float t[32][33];
    int f0 = blockIdx.x * 32, o0 = blockIdx.y * 32, leaf = blockIdx.z;
    int j = threadIdx.x & 31, i0 = threadIdx.x >> 5;
    const float* src = lw + (size_t)leaf * FEAT * LDIM;
#pragma unroll
    for (int p = 0; p < 4; p++) {
        int i = i0 + p * 8;
        t[i][j] = src[(size_t)(f0 + i) * LDIM + o0 + j];
    }
    __syncthreads();
    __half* dst = g_wh + (size_t)leaf * LDIM * FEAT;
#pragma unroll
    for (int p = 0; p < 4; p++) {
        int i = i0 + p * 8;
        dst[(size_t)(o0 + i) * FEAT + f0 + j] = __float2half_rn(t[j][i]);
    }
}

__global__ void k_dw(const float* __restrict__ rw) {
    int i = blockIdx.x * blockDim.x + threadIdx.x;  // 65536
    int f = i >> 6, n = i & 63;
    float v = 0.f;
    if (n < NINT) v = rw[(n * FEAT + f) * 2] - rw[(n * FEAT + f) * 2 + 1];
    g_dw[f * 64 + n] = v;
}

// ---------------- routing GEMM (fp32 FFMA, deterministic split-K x4) ----------------
__global__ __launch_bounds__(256) void k_rout(const float* __restrict__ x) {
    __shared__ float Xs[2][64][20];
    __shared__ float Ds[2][16][68];
    int tid = threadIdx.x;
    int r0 = blockIdx.x * 64;
    int kc = blockIdx.y * 256;
    int rg = tid >> 4, cg = tid & 15;
    float acc[4][4];
#pragma unroll
    for (int i = 0; i < 4; i++)
#pragma unroll
        for (int j = 0; j < 4; j++) acc[i][j] = 0.f;

    auto load = [&](int s, int k0) {
        {
            int row = tid >> 2, ko = (tid & 3) << 2;
            cp16(&Xs[s][row][ko], x + (size_t)(r0 + row) * FEAT + kc + k0 + ko);
        }
        {
            int row = tid >> 4, no = (tid & 15) << 2;
            cp16(&Ds[s][row][no], g_dw + (kc + k0 + row) * 64 + no);
        }
    };
    load(0, 0); cp_commit();
    load(1, 16); cp_commit();
    cp_wait<1>();
    __syncthreads();

    for (int kt = 0; kt < 16; kt++) {
        int s = kt & 1;
#pragma unroll
        for (int k = 0; k < 16; k++) {
            float4 b = *(const float4*)&Ds[s][k][cg << 2];
#pragma unroll
            for (int i = 0; i < 4; i++) {
                float a = Xs[s][(rg << 2) + i][k];
                acc[i][0] += a * b.x; acc[i][1] += a * b.y;
                acc[i][2] += a * b.z; acc[i][3] += a * b.w;
            }
        }
        __syncthreads();
        if (kt + 2 < 16) load(s, (kt + 2) * 16);
        cp_commit();
        cp_wait<1>();
        __syncthreads();
    }
#pragma unroll
    for (int i = 0; i < 4; i++) {
        float4 v = make_float4(acc[i][0], acc[i][1], acc[i][2], acc[i][3]);
        *(float4*)&g_part[blockIdx.y][(size_t)(r0 + (rg << 2) + i) * 64 + (cg << 2)] = v;
    }
}

// ---------------- leaf probs ----------------
__global__ void k_leaf() {
    __shared__ float ps[8][64];
    int tid = threadIdx.x;  // 512
    int rb = blockIdx.x * 8;
    int r = tid >> 6, n = tid & 63;
    if (n < NINT) {
        size_t idx = (size_t)(rb + r) * 64 + n;
        float s = g_part[0][idx] + g_part[1][idx] + g_part[2][idx] + g_part[3][idx];
        ps[r][n] = 1.f / (1.f + __expf(-s));
    }
    __syncthreads();
    int l = n;
    float prob = 1.f;
#pragma unroll
    for (int d = 0; d < 6; d++) {
        int node = (1 << d) - 1 + (l >> (6 - d));
        int dir = (l >> (5 - d)) & 1;
        float p = ps[r][node];
        prob *= dir ? (1.f - p) : p;
    }
    g_lp[(size_t)(rb + r) * 64 + l] = prob;
}

// ---------------- main GEMM: fp16 mma.sync + TMA SW128 pipeline ----------------
// 128x128 tile, BK=64, 3-stage ring. Warps 0-7 compute, warp 8 = TMA producer.
#define BK 64
#define NSTAGE 3
#define STAGE_B 16384            // 128 rows x 128 bytes
#define OFF_BSTG (NSTAGE * STAGE_B)        // 49152
#define OFF_MBAR (2 * NSTAGE * STAGE_B)    // 98304: full[3], empty[3]
#define SMEM_RAW (OFF_MBAR + 64 + 1024)    // +1KB for in-kernel 1024-alignment

__global__ __launch_bounds__(288, 2) void k_main(
    const __grid_constant__ CUtensorMap tma_a,
    const __grid_constant__ CUtensorMap tma_b,
    const float* __restrict__ bias, float* __restrict__ out)
{
    extern __shared__ char smem_raw[];
    uint32_t sb = (smem_u32(smem_raw) + 1023u) & ~1023u;   // 1KB-align for SW128
    const int tid = threadIdx.x, lane = tid & 31, wid = tid >> 5;
    const int leaf = blockIdx.x;
    const int bm0 = blockIdx.y * 128;

    if (tid == 0) {
#pragma unroll
        for (int s = 0; s < NSTAGE; s++) {
            MBAR_INIT(sb + OFF_MBAR + s * 8, 1);         // full: 1 expect_tx arrival
            MBAR_INIT(sb + OFF_MBAR + 24 + s * 8, 256);  // empty: 256 compute threads
        }
    }
    __syncthreads();

    if (wid == 8) {
        // ---- producer ----
        if (elect_one()) {
            int phase = 1, slot = 0;
            for (int s = 0; s < FEAT / BK; s++) {
                mbar_wait(sb + OFF_MBAR + 24 + slot * 8, phase);
                MBAR_EXPECT_TX(sb + OFF_MBAR + slot * 8, 2 * STAGE_B);
                tma2d(sb + slot * STAGE_B, &tma_a, s * BK, bm0, sb + OFF_MBAR + slot * 8);
                tma2d(sb + OFF_BSTG + slot * STAGE_B, &tma_b, s * BK, leaf * 128,
                      sb + OFF_MBAR + slot * 8);
                if (++slot == NSTAGE) { slot = 0; phase ^= 1; }
            }
        }
        return;
    }

    // ---- compute warps (0-7) ----
    const int mw = (wid & 3) * 32, nw = (wid >> 2) * 64;
    const int g = lane >> 2, cc = lane & 3;
    const int lr = lane & 7, grp = lane >> 3;
    const uint32_t xr = (uint32_t)lr << 4;   // SW128 xor constant: (row&7)<<4

    // lane base offsets within a stage (bytes)
    const uint32_t a_row = mw + (grp & 1) * 8 + lr;
    const uint32_t b_row = nw + (grp >> 1) * 8 + lr;
    const uint32_t a_rbase = a_row * 128;
    const uint32_t b_rbase = b_row * 128;
    const uint32_t a_cb0 = (uint32_t)(grp >> 1) * 16;   // col byte before ks
    const uint32_t b_cb0 = (uint32_t)(grp & 1) * 16;

    float acc[2][8][4];
#pragma unroll
    for (int a = 0; a < 2; a++)
#pragma unroll
        for (int b = 0; b < 8; b++)
#pragma unroll
            for (int c = 0; c < 4; c++) acc[a][b][c] = 0.f;

    int phase = 0, slot = 0;
    for (int kt = 0; kt < FEAT / BK; kt++) {
        mbar_wait(sb + OFF_MBAR + slot * 8, phase);
        uint32_t abase = sb + slot * STAGE_B + a_rbase;
        uint32_t bbase = sb + OFF_BSTG + slot * STAGE_B + b_rbase;
#pragma unroll
        for (int ks = 0; ks < 4; ks++) {
            uint32_t acb = (a_cb0 + ks * 32) ^ xr;
            uint32_t bcb = (b_cb0 + ks * 32) ^ xr;
            uint32_t a[2][4], b[4][4];
            ldm4(a[0], abase + acb);
            ldm4(a[1], abase + 16 * 128 + acb);
#pragma unroll
            for (int pn = 0; pn < 4; pn++)
                ldm4(b[pn], bbase + pn * 16 * 128 + bcb);
#pragma unroll
            for (int nt = 0; nt < 8; nt++) {
                int pn = nt >> 1, hi = (nt & 1) << 1;
                mma_f16(acc[0][nt], a[0], b[pn][hi], b[pn][hi + 1]);
                mma_f16(acc[1][nt], a[1], b[pn][hi], b[pn][hi + 1]);
            }
        }
        MBAR_ARRIVE(sb + OFF_MBAR + 24 + slot * 8);
        if (++slot == NSTAGE) { slot = 0; phase ^= 1; }
    }

    // ---- epilogue: out = p[row,leaf] * (acc + bias[leaf,col]) ----
#pragma unroll
    for (int mt = 0; mt < 2; mt++) {
        int r0 = bm0 + mw + mt * 16 + g;
        float p0 = g_lp[(size_t)r0 * 64 + leaf];
        float p1 = g_lp[(size_t)(r0 + 8) * 64 + leaf];
#pragma unroll
        for (int nt = 0; nt < 8; nt++) {
            int col = nw + nt * 8 + 2 * cc;
            float b0 = bias[leaf * LDIM + col];
            float b1 = bias[leaf * LDIM + col + 1];
            int gc = leaf * LDIM + col;
            float2 v0 = make_float2(p0 * (acc[mt][nt][0] + b0), p0 * (acc[mt][nt][1] + b1));
            float2 v1 = make_float2(p1 * (acc[mt][nt][2] + b0), p1 * (acc[mt][nt][3] + b1));
            *(float2*)(out + (size_t)r0 * OUTD + gc) = v0;
            *(float2*)(out + (size_t)(r0 + 8) * OUTD + gc) = v1;
        }
    }
}

// ---------------- host ----------------
typedef CUresult (*PFN_encodeTiled)(CUtensorMap*, CUtensorMapDataType, cuuint32_t, void*,
                                    const cuuint64_t*, const cuuint64_t*, const cuuint32_t*,
                                    const cuuint32_t*, CUtensorMapInterleave, CUtensorMapSwizzle,
                                    CUtensorMapL2promotion, CUtensorMapFloatOOBfill);

static void make_map(PFN_encodeTiled enc, CUtensorMap* m, void* base) {
    cuuint64_t dims[2] = {FEAT, 8192};                 // halves, rows
    cuuint64_t strides[1] = {FEAT * sizeof(__half)};   // 2048 B
    cuuint32_t box[2] = {BK, 128};                     // 64 halves = 128 B inner
    cuuint32_t es[2] = {1, 1};
    enc(m, CU_TENSOR_MAP_DATA_TYPE_UINT16, 2, base, dims, strides, box, es,
        CU_TENSOR_MAP_INTERLEAVE_NONE, CU_TENSOR_MAP_SWIZZLE_128B,
        CU_TENSOR_MAP_L2_PROMOTION_L2_128B, CU_TENSOR_MAP_FLOAT_OOB_FILL_NONE);
}

extern "C" void kernel_launch(void* const* d_in, const int* in_sizes, int n_in,
                              void* d_out, int out_size) {
    const float* x  = (const float*)d_in[0];
    const float* rw = (const float*)d_in[1];
    const float* lw = (const float*)d_in[2];
    const float* lb = (const float*)d_in[3];
    float* out = (float*)d_out;
    (void)in_sizes; (void)n_in; (void)out_size;

    PFN_encodeTiled enc = nullptr;
    cudaDriverEntryPointQueryResult qr;
    cudaGetDriverEntryPoint("cuTensorMapEncodeTiled", (void**)&enc, cudaEnableDefault, &qr);

    void* xh_ptr = nullptr;
    void* wh_ptr = nullptr;
    cudaGetSymbolAddress(&xh_ptr, g_xh);
    cudaGetSymbolAddress(&wh_ptr, g_wh);

    CUtensorMap tma_a, tma_b;
    make_map(enc, &tma_a, xh_ptr);
    make_map(enc, &tma_b, wh_ptr);

    cudaFuncSetAttribute(k_main, cudaFuncAttributeMaxDynamicSharedMemorySize, SMEM_RAW);

    k_cvt_h<<<8192, 256>>>((const float4*)x);
    k_wt_h<<<dim3(32, 4, 64), 256>>>(lw);
    k_dw<<<256, 256>>>(rw);
    k_rout<<<dim3(128, 4), 256>>>(x);
    k_leaf<<<1024, 512>>>();
    k_main<<<dim3(64, 64), 288, SMEM_RAW>>>(tma_a, tma_b, lb, out);
}

// round 6
// speedup vs baseline: 2.6846x; 1.0695x over previous
#include <cuda_runtime.h>
#include <cuda.h>
#include <cuda_fp16.h>
#include <cstdint>

#define BATCH 8192
#define FEAT  1024
#define NLEAF 64
#define LDIM  128
#define OUTD  8192
#define NINT  63

// ---------------- device scratch (no allocations) ----------------
__device__ __half g_xh[BATCH * FEAT];          // fp16 x, row-major [8192][1024]   (16 MB)
__device__ __half g_wh[NLEAF * LDIM * FEAT];   // fp16 W^T, [leaf][o][f]           (16 MB)
__device__ __half g_dwh[64 * FEAT];            // fp16 routing diff W, [n][f] K-major
__device__ float g_lg[BATCH * 64];             // routing logits (2 MB)
__device__ float g_lp[BATCH * 64];             // leaf probs (2 MB)

// ---------------- PTX helpers ----------------
__device__ __forceinline__ uint32_t smem_u32(const void* p) {
    uint32_t a;
    asm("{ .reg .u64 t; cvta.to.shared.u64 t, %1; cvt.u32.u64 %0, t; }" : "=r"(a) : "l"(p));
    return a;
}
__device__ __forceinline__ uint32_t elect_one() {
    uint32_t p;
    asm volatile("{\n\t.reg .pred p;\n\telect.sync _|p, 0xFFFFFFFF;\n\tselp.b32 %0, 1, 0, p;\n\t}" : "=r"(p));
    return p;
}

#define MBAR_INIT(a, c) asm volatile("mbarrier.init.shared.b64 [%0], %1;" ::"r"(a), "r"(c) : "memory")
#define MBAR_EXPECT_TX(a, n) asm volatile("mbarrier.arrive.expect_tx.shared.b64 _, [%0], %1;" ::"r"(a), "r"(n) : "memory")
#define MBAR_ARRIVE(a) asm volatile("mbarrier.arrive.shared.b64 _, [%0];" ::"r"(a) : "memory")

__device__ __forceinline__ void mbar_wait(uint32_t mbar, uint32_t parity) {
    uint32_t done;
    asm volatile(
        "{\n\t.reg .pred p;\n\t"
        "mbarrier.try_wait.parity.acquire.cta.shared::cta.b64 p, [%1], %2;\n\t"
        "selp.b32 %0, 1, 0, p;\n\t}"
        : "=r"(done) : "r"(mbar), "r"(parity) : "memory");
    if (!done) {
        asm volatile(
            "{\n\t.reg .pred P1;\n\t"
            "WL_%=:\n\t"
            "mbarrier.try_wait.parity.acquire.cta.shared::cta.b64 P1, [%0], %1, 0x989680;\n\t"
            "@P1 bra.uni WD_%=;\n\t"
            "bra.uni WL_%=;\n\t"
            "WD_%=:\n\t}"
            :: "r"(mbar), "r"(parity) : "memory");
    }
}

__device__ __forceinline__ void tma2d(uint32_t sa, const void* map, int cx, int cy, uint32_t mb) {
    asm volatile(
        "cp.async.bulk.tensor.2d.shared::cta.global.tile.mbarrier::complete_tx::bytes "
        "[%0], [%1, {%2, %3}], [%4];"
        :: "r"(sa), "l"(map), "r"(cx), "r"(cy), "r"(mb) : "memory");
}

__device__ __forceinline__ void ldm4(uint32_t* r, uint32_t addr) {
    asm volatile("ldmatrix.sync.aligned.m8n8.x4.shared.b16 {%0,%1,%2,%3}, [%4];"
        : "=r"(r[0]), "=r"(r[1]), "=r"(r[2]), "=r"(r[3]) : "r"(addr));
}
__device__ __forceinline__ void mma_f16(float* c, const uint32_t* a, uint32_t b0, uint32_t b1) {
    asm volatile(
        "mma.sync.aligned.m16n8k16.row.col.f32.f16.f16.f32 "
        "{%0,%1,%2,%3}, {%4,%5,%6,%7}, {%8,%9}, {%0,%1,%2,%3};\n"
        : "+f"(c[0]), "+f"(c[1]), "+f"(c[2]), "+f"(c[3])
        : "r"(a[0]), "r"(a[1]), "r"(a[2]), "r"(a[3]), "r"(b0), "r"(b1));
}

// ---------------- prep: fp32 -> fp16 (rn) ----------------
__global__ void k_cvt_h(const float4* __restrict__ src) {
    int i = blockIdx.x * blockDim.x + threadIdx.x;  // 2097152 threads = 8M floats
    float4 v = src[i];
    __half2 h0 = __floats2half2_rn(v.x, v.y);
    __half2 h1 = __floats2half2_rn(v.z, v.w);
    uint2 o;
    o.x = *(uint32_t*)&h0;
    o.y = *(uint32_t*)&h1;
    ((uint2*)g_xh)[i] = o;
}

// W transpose + fp16 round: lw[leaf][f][o] -> g_wh[leaf][o][f]
__global__ void k_wt_h(const float* __restrict__ lw) {
    __shared__ float t[32][33];
    int f0 = blockIdx.x * 32, o0 = blockIdx.y * 32, leaf = blockIdx.z;
    int j = threadIdx.x & 31, i0 = threadIdx.x >> 5;
    const float* src = lw + (size_t)leaf * FEAT * LDIM;
#pragma unroll
    for (int p = 0; p < 4; p++) {
        int i = i0 + p * 8;
        t[i][j] = src[(size_t)(f0 + i) * LDIM + o0 + j];
    }
    __syncthreads();
    __half* dst = g_wh + (size_t)leaf * LDIM * FEAT;
#pragma unroll
    for (int p = 0; p < 4; p++) {
        int i = i0 + p * 8;
        dst[(size_t)(o0 + i) * FEAT + f0 + j] = __float2half_rn(t[j][i]);
    }
}

// routing diff weights, fp16, [n][f] K-major: g_dwh[n][f] = rw[n,f,0]-rw[n,f,1]
__global__ void k_dwh(const float* __restrict__ rw) {
    int i = blockIdx.x * blockDim.x + threadIdx.x;  // 65536
    int n = i >> 10, f = i & 1023;
    float v = 0.f;
    if (n < NINT) v = rw[(n * FEAT + f) * 2] - rw[(n * FEAT + f) * 2 + 1];
    g_dwh[n * FEAT + f] = __float2half_rn(v);
}

// ---------------- shared pipeline constants ----------------
#define BK 64
#define NSTAGE 3
#define STAGE_B 16384            // 128 rows x 128 bytes

// ---------------- routing GEMM: fp16 mma + TMA, 128x64 tiles ----------------
#define R_BSTAGE 8192                          // 64 rows x 128 bytes
#define R_OFF_B (NSTAGE * STAGE_B)             // 49152
#define R_OFF_MBAR (R_OFF_B + NSTAGE * R_BSTAGE)   // 73728
#define R_SMEM (R_OFF_MBAR + 64 + 1024)

__global__ __launch_bounds__(288, 2) void k_rgemm(
    const __grid_constant__ CUtensorMap tma_a,
    const __grid_constant__ CUtensorMap tma_b)
{
    extern __shared__ char smem_raw[];
    uint32_t sb = (smem_u32(smem_raw) + 1023u) & ~1023u;
    const int tid = threadIdx.x, lane = tid & 31, wid = tid >> 5;
    const int bm0 = blockIdx.x * 128;

    if (tid == 0) {
#pragma unroll
        for (int s = 0; s < NSTAGE; s++) {
            MBAR_INIT(sb + R_OFF_MBAR + s * 8, 1);
            MBAR_INIT(sb + R_OFF_MBAR + 24 + s * 8, 256);
        }
    }
    __syncthreads();

    if (wid == 8) {
        if (elect_one()) {
            int phase = 1, slot = 0;
            for (int s = 0; s < FEAT / BK; s++) {
                mbar_wait(sb + R_OFF_MBAR + 24 + slot * 8, phase);
                MBAR_EXPECT_TX(sb + R_OFF_MBAR + slot * 8, STAGE_B + R_BSTAGE);
                tma2d(sb + slot * STAGE_B, &tma_a, s * BK, bm0, sb + R_OFF_MBAR + slot * 8);
                tma2d(sb + R_OFF_B + slot * R_BSTAGE, &tma_b, s * BK, 0,
                      sb + R_OFF_MBAR + slot * 8);
                if (++slot == NSTAGE) { slot = 0; phase ^= 1; }
            }
        }
        return;
    }

    // compute: 8 warps, each 16 rows x 64 cols
    const int mw = wid * 16;
    const int g = lane >> 2, cc = lane & 3;
    const int lr = lane & 7, grp = lane >> 3;
    const uint32_t xr = (uint32_t)lr << 4;
    const uint32_t a_rbase = (mw + (grp & 1) * 8 + lr) * 128;
    const uint32_t b_rbase = ((grp >> 1) * 8 + lr) * 128;
    const uint32_t a_cb0 = (uint32_t)(grp >> 1) * 16;
    const uint32_t b_cb0 = (uint32_t)(grp & 1) * 16;

    float acc[8][4];
#pragma unroll
    for (int b = 0; b < 8; b++)
#pragma unroll
        for (int c = 0; c < 4; c++) acc[b][c] = 0.f;

    int phase = 0, slot = 0;
    for (int kt = 0; kt < FEAT / BK; kt++) {
        mbar_wait(sb + R_OFF_MBAR + slot * 8, phase);
        uint32_t abase = sb + slot * STAGE_B + a_rbase;
        uint32_t bbase = sb + R_OFF_B + slot * R_BSTAGE + b_rbase;
#pragma unroll
        for (int ks = 0; ks < 4; ks++) {
            uint32_t acb = (a_cb0 + ks * 32) ^ xr;
            uint32_t bcb = (b_cb0 + ks * 32) ^ xr;
            uint32_t a[4], b[4][4];
            ldm4(a, abase + acb);
#pragma unroll
            for (int pn = 0; pn < 4; pn++)
                ldm4(b[pn], bbase + pn * 16 * 128 + bcb);
#pragma unroll
            for (int nt = 0; nt < 8; nt++) {
                int pn = nt >> 1, hi = (nt & 1) << 1;
                mma_f16(acc[nt], a, b[pn][hi], b[pn][hi + 1]);
            }
        }
        MBAR_ARRIVE(sb + R_OFF_MBAR + 24 + slot * 8);
        if (++slot == NSTAGE) { slot = 0; phase ^= 1; }
    }

    // write logits
    int r0 = bm0 + mw + g;
#pragma unroll
    for (int nt = 0; nt < 8; nt++) {
        int col = nt * 8 + 2 * cc;
        *(float2*)(g_lg + (size_t)r0 * 64 + col) = make_float2(acc[nt][0], acc[nt][1]);
        *(float2*)(g_lg + (size_t)(r0 + 8) * 64 + col) = make_float2(acc[nt][2], acc[nt][3]);
    }
}

// ---------------- leaf probs ----------------
__global__ void k_leaf() {
    __shared__ float ps[8][64];
    int tid = threadIdx.x;  // 512
    int rb = blockIdx.x * 8;
    int r = tid >> 6, n = tid & 63;
    if (n < NINT) {
        float s = g_lg[(size_t)(rb + r) * 64 + n];
        ps[r][n] = 1.f / (1.f + __expf(-s));
    }
    __syncthreads();
    int l = n;
    float prob = 1.f;
#pragma unroll
    for (int d = 0; d < 6; d++) {
        int node = (1 << d) - 1 + (l >> (6 - d));
        int dir = (l >> (5 - d)) & 1;
        float p = ps[r][node];
        prob *= dir ? (1.f - p) : p;
    }
    g_lp[(size_t)(rb + r) * 64 + l] = prob;
}

// ---------------- main GEMM: fp16 mma.sync + TMA SW128 pipeline ----------------
#define OFF_BSTG (NSTAGE * STAGE_B)        // 49152
#define OFF_MBAR (2 * NSTAGE * STAGE_B)    // 98304: full[3], empty[3]
#define SMEM_RAW (OFF_MBAR + 64 + 1024)

__global__ __launch_bounds__(288, 2) void k_main(
    const __grid_constant__ CUtensorMap tma_a,
    const __grid_constant__ CUtensorMap tma_b,
    const float* __restrict__ bias, float* __restrict__ out)
{
    extern __shared__ char smem_raw[];
    uint32_t sb = (smem_u32(smem_raw) + 1023u) & ~1023u;
    const int tid = threadIdx.x, lane = tid & 31, wid = tid >> 5;
    const int leaf = blockIdx.x;
    const int bm0 = blockIdx.y * 128;

    if (tid == 0) {
#pragma unroll
        for (int s = 0; s < NSTAGE; s++) {
            MBAR_INIT(sb + OFF_MBAR + s * 8, 1);
            MBAR_INIT(sb + OFF_MBAR + 24 + s * 8, 256);
        }
    }
    __syncthreads();

    if (wid == 8) {
        if (elect_one()) {
            int phase = 1, slot = 0;
            for (int s = 0; s < FEAT / BK; s++) {
                mbar_wait(sb + OFF_MBAR + 24 + slot * 8, phase);
                MBAR_EXPECT_TX(sb + OFF_MBAR + slot * 8, 2 * STAGE_B);
                tma2d(sb + slot * STAGE_B, &tma_a, s * BK, bm0, sb + OFF_MBAR + slot * 8);
                tma2d(sb + OFF_BSTG + slot * STAGE_B, &tma_b, s * BK, leaf * 128,
                      sb + OFF_MBAR + slot * 8);
                if (++slot == NSTAGE) { slot = 0; phase ^= 1; }
            }
        }
        return;
    }

    const int mw = (wid & 3) * 32, nw = (wid >> 2) * 64;
    const int g = lane >> 2, cc = lane & 3;
    const int lr = lane & 7, grp = lane >> 3;
    const uint32_t xr = (uint32_t)lr << 4;
    const uint32_t a_rbase = (mw + (grp & 1) * 8 + lr) * 128;
    const uint32_t b_rbase = (nw + (grp >> 1) * 8 + lr) * 128;
    const uint32_t a_cb0 = (uint32_t)(grp >> 1) * 16;
    const uint32_t b_cb0 = (uint32_t)(grp & 1) * 16;

    float acc[2][8][4];
#pragma unroll
    for (int a = 0; a < 2; a++)
#pragma unroll
        for (int b = 0; b < 8; b++)
#pragma unroll
            for (int c = 0; c < 4; c++) acc[a][b][c] = 0.f;

    int phase = 0, slot = 0;
    for (int kt = 0; kt < FEAT / BK; kt++) {
        mbar_wait(sb + OFF_MBAR + slot * 8, phase);
        uint32_t abase = sb + slot * STAGE_B + a_rbase;
        uint32_t bbase = sb + OFF_BSTG + slot * STAGE_B + b_rbase;
#pragma unroll
        for (int ks = 0; ks < 4; ks++) {
            uint32_t acb = (a_cb0 + ks * 32) ^ xr;
            uint32_t bcb = (b_cb0 + ks * 32) ^ xr;
            uint32_t a[2][4], b[4][4];
            ldm4(a[0], abase + acb);
            ldm4(a[1], abase + 16 * 128 + acb);
#pragma unroll
            for (int pn = 0; pn < 4; pn++)
                ldm4(b[pn], bbase + pn * 16 * 128 + bcb);
#pragma unroll
            for (int nt = 0; nt < 8; nt++) {
                int pn = nt >> 1, hi = (nt & 1) << 1;
                mma_f16(acc[0][nt], a[0], b[pn][hi], b[pn][hi + 1]);
                mma_f16(acc[1][nt], a[1], b[pn][hi], b[pn][hi + 1]);
            }
        }
        MBAR_ARRIVE(sb + OFF_MBAR + 24 + slot * 8);
        if (++slot == NSTAGE) { slot = 0; phase ^= 1; }
    }

#pragma unroll
    for (int mt = 0; mt < 2; mt++) {
        int r0 = bm0 + mw + mt * 16 + g;
        float p0 = g_lp[(size_t)r0 * 64 + leaf];
        float p1 = g_lp[(size_t)(r0 + 8) * 64 + leaf];
#pragma unroll
        for (int nt = 0; nt < 8; nt++) {
            int col = nw + nt * 8 + 2 * cc;
            float b0 = bias[leaf * LDIM + col];
            float b1 = bias[leaf * LDIM + col + 1];
            int gc = leaf * LDIM + col;
            float2 v0 = make_float2(p0 * (acc[mt][nt][0] + b0), p0 * (acc[mt][nt][1] + b1));
            float2 v1 = make_float2(p1 * (acc[mt][nt][2] + b0), p1 * (acc[mt][nt][3] + b1));
            *(float2*)(out + (size_t)r0 * OUTD + gc) = v0;
            *(float2*)(out + (size_t)(r0 + 8) * OUTD + gc) = v1;
        }
    }
}

// ---------------- host ----------------
typedef CUresult (*PFN_encodeTiled)(CUtensorMap*, CUtensorMapDataType, cuuint32_t, void*,
                                    const cuuint64_t*, const cuuint64_t*, const cuuint32_t*,
                                    const cuuint32_t*, CUtensorMapInterleave, CUtensorMapSwizzle,
                                    CUtensorMapL2promotion, CUtensorMapFloatOOBfill);

static void make_map(PFN_encodeTiled enc, CUtensorMap* m, void* base,
                     cuuint64_t rows, cuuint32_t box_rows) {
    cuuint64_t dims[2] = {FEAT, rows};
    cuuint64_t strides[1] = {FEAT * sizeof(__half)};
    cuuint32_t box[2] = {BK, box_rows};
    cuuint32_t es[2] = {1, 1};
    enc(m, CU_TENSOR_MAP_DATA_TYPE_UINT16, 2, base, dims, strides, box, es,
        CU_TENSOR_MAP_INTERLEAVE_NONE, CU_TENSOR_MAP_SWIZZLE_128B,
        CU_TENSOR_MAP_L2_PROMOTION_L2_128B, CU_TENSOR_MAP_FLOAT_OOB_FILL_NONE);
}

extern "C" void kernel_launch(void* const* d_in, const int* in_sizes, int n_in,
                              void* d_out, int out_size) {
    const float* x  = (const float*)d_in[0];
    const float* rw = (const float*)d_in[1];
    const float* lw = (const float*)d_in[2];
    const float* lb = (const float*)d_in[3];
    float* out = (float*)d_out;
    (void)in_sizes; (void)n_in; (void)out_size;

    PFN_encodeTiled enc = nullptr;
    cudaDriverEntryPointQueryResult qr;
    cudaGetDriverEntryPoint("cuTensorMapEncodeTiled", (void**)&enc, cudaEnableDefault, &qr);

    void* xh_ptr = nullptr; void* wh_ptr = nullptr; void* dwh_ptr = nullptr;
    cudaGetSymbolAddress(&xh_ptr, g_xh);
    cudaGetSymbolAddress(&wh_ptr, g_wh);
    cudaGetSymbolAddress(&dwh_ptr, g_dwh);

    CUtensorMap tma_a, tma_b, tma_d;
    make_map(enc, &tma_a, xh_ptr, 8192, 128);
    make_map(enc, &tma_b, wh_ptr, 8192, 128);
    make_map(enc, &tma_d, dwh_ptr, 64, 64);

    cudaFuncSetAttribute(k_main, cudaFuncAttributeMaxDynamicSharedMemorySize, SMEM_RAW);
    cudaFuncSetAttribute(k_rgemm, cudaFuncAttributeMaxDynamicSharedMemorySize, R_SMEM);

    k_cvt_h<<<8192, 256>>>((const float4*)x);
    k_wt_h<<<dim3(32, 4, 64), 256>>>(lw);
    k_dwh<<<256, 256>>>(rw);
    k_rgemm<<<64, 288, R_SMEM>>>(tma_a, tma_d);
    k_leaf<<<1024, 512>>>();
    k_main<<<dim3(64, 64), 288, SMEM_RAW>>>(tma_a, tma_b, lb, out);
}